// round 13
// baseline (speedup 1.0000x reference)
#include <cuda_runtime.h>
#include <cuda_bf16.h>
#include <cstdint>

#define NN 50000
#define EPMAX 850000
#define NEG_SLOPE 0.2f
#define NB_SCAN 98    // ceil(50000/512)

// ---------------- scratch (device globals; no allocation allowed) ----------------
__device__ __align__(16) float g_z0[NN * 128];
__device__ __align__(16) float g_h0[NN * 128];
__device__ __align__(16) float g_z1[NN * 40];
__device__ __align__(16) float g_el[NN * 4];
__device__ __align__(16) float g_er[NN * 4];
__device__ int g_cnt[NN];      // in-degree; all-zero at entry of every call (invariant)
__device__ int g_rowptr[NN];
__device__ int g_srcs[EPMAX];
__device__ int g_epos[EPMAX];  // per-edge position within destination segment
// preconverted weights (bf16 hi/lo, transposed to [n][k])
__device__ __align__(16) __nv_bfloat16 gW0h[128 * 256];
__device__ __align__(16) __nv_bfloat16 gW0l[128 * 256];
__device__ __align__(16) __nv_bfloat16 gW1h[40 * 128];
__device__ __align__(16) __nv_bfloat16 gW1l[40 * 128];

// ================= MMA / LDSM helpers =================
__device__ __forceinline__ void mma_bf16(float& c0, float& c1, float& c2, float& c3,
                                         uint32_t a0, uint32_t a1, uint32_t a2, uint32_t a3,
                                         uint32_t b0, uint32_t b1) {
    asm volatile(
        "mma.sync.aligned.m16n8k16.row.col.f32.bf16.bf16.f32 "
        "{%0,%1,%2,%3}, {%4,%5,%6,%7}, {%8,%9}, {%0,%1,%2,%3};"
        : "+f"(c0), "+f"(c1), "+f"(c2), "+f"(c3)
        : "r"(a0), "r"(a1), "r"(a2), "r"(a3), "r"(b0), "r"(b1));
}

__device__ __forceinline__ void ldsm_x4(uint32_t& r0, uint32_t& r1, uint32_t& r2, uint32_t& r3,
                                        uint32_t addr) {
    asm volatile("ldmatrix.sync.aligned.m8n8.x4.shared.b16 {%0,%1,%2,%3}, [%4];"
                 : "=r"(r0), "=r"(r1), "=r"(r2), "=r"(r3) : "r"(addr));
}

__device__ __forceinline__ uint32_t smem_u32(const void* p) {
    return (uint32_t)__cvta_generic_to_shared(p);
}

// ================= wconv: one-time weight split (W0 and W1) =================
__global__ void wconv_kernel(const float* __restrict__ W0, const float* __restrict__ W1) {
    int i = blockIdx.x * blockDim.x + threadIdx.x;
    if (i < 128 * 256) {
        int k = i >> 7, n = i & 127;          // W0[k][n], k<256
        float v = W0[k * 128 + n];
        __nv_bfloat16 h = __float2bfloat16_rn(v);
        gW0h[n * 256 + k] = h;
        gW0l[n * 256 + k] = __float2bfloat16_rn(v - __bfloat162float(h));
    } else if (i < 128 * 256 + 128 * 40) {
        int j = i - 128 * 256;
        int k = j / 40, n = j % 40;           // W1[k][n], k<128
        float v = W1[k * 40 + n];
        __nv_bfloat16 h = __float2bfloat16_rn(v);
        gW1h[n * 128 + k] = h;
        gW1l[n * 128 + k] = __float2bfloat16_rn(v - __bfloat162float(h));
    }
}

// ================= gemm0: g_z0 = x @ W0 (+fused attn0), BM=128, ldmatrix frags =================
#define G0_K 256
#define G0_PAD 40

__global__ void __launch_bounds__(256) gemm0_mma_kernel(const float* __restrict__ A,
                                                        const float* __restrict__ al0,
                                                        const float* __restrict__ ar0,
                                                        int nrows) {
    __shared__ __nv_bfloat16 Ah[128][G0_PAD];
    __shared__ __nv_bfloat16 Al[128][G0_PAD];
    __shared__ __nv_bfloat16 Bh[128][G0_PAD];   // [n][k'] tile
    __shared__ __nv_bfloat16 Bl[128][G0_PAD];

    const int tid = threadIdx.x;
    const int lane = tid & 31;
    const int wid = tid >> 5;
    const int warp_m = wid & 3;         // 4 warps over 128 rows
    const int warp_n = wid >> 2;        // 2 warps over 128 cols (64 each)
    const int rowBase = blockIdx.x * 128;
    const int g = lane >> 2;
    const int q = lane & 3;

    // ---- precomputed ldmatrix lane addresses (byte offsets within smem) ----
    // A (m16k16 x4): matrices {rows 0-7,k0}{rows 8-15,k0}{rows 0-7,k8}{rows 8-15,k8}
    const int aRowOff = (lane & 7) + ((lane >> 3) & 1) * 8;
    const int aColB   = ((lane >> 4) & 1) * 16;
    uint32_t adAh[2], adAl[2];
#pragma unroll
    for (int mt = 0; mt < 2; mt++) {
        int r = warp_m * 32 + mt * 16 + aRowOff;
        adAh[mt] = smem_u32(&Ah[r][0]) + aColB;
        adAl[mt] = smem_u32(&Al[r][0]) + aColB;
    }
    // B (two n8k16 frags per x4): matrices {nt=2p,k0}{nt=2p,k8}{nt=2p+1,k0}{nt=2p+1,k8}
    const int bm = lane >> 3;
    const int bRowOff = (bm >> 1) * 8 + (lane & 7);
    const int bColB = (bm & 1) * 16;
    uint32_t adBh[4], adBl[4];
#pragma unroll
    for (int p = 0; p < 4; p++) {
        int r = warp_n * 64 + p * 16 + bRowOff;
        adBh[p] = smem_u32(&Bh[r][0]) + bColB;
        adBl[p] = smem_u32(&Bl[r][0]) + bColB;
    }

    float acc[2][8][4];
#pragma unroll
    for (int mt = 0; mt < 2; mt++)
#pragma unroll
        for (int nt = 0; nt < 8; nt++)
#pragma unroll
            for (int i = 0; i < 4; i++) acc[mt][nt][i] = 0.f;

    for (int kt = 0; kt < G0_K / 32; kt++) {
        // ---- A tile 128x32 fp32 -> bf16 hi/lo ----
#pragma unroll
        for (int i = 0; i < 4; i++) {
            int idx = tid + i * 256;
            int row = idx >> 3;
            int kq  = idx & 7;
            float4 v = make_float4(0.f, 0.f, 0.f, 0.f);
            if (rowBase + row < nrows)
                v = *(const float4*)(A + (size_t)(rowBase + row) * G0_K + kt * 32 + kq * 4);
            int kl = kq * 4;
            const float vv[4] = {v.x, v.y, v.z, v.w};
#pragma unroll
            for (int j = 0; j < 4; j++) {
                __nv_bfloat16 h = __float2bfloat16_rn(vv[j]);
                Ah[row][kl + j] = h;
                Al[row][kl + j] = __float2bfloat16_rn(vv[j] - __bfloat162float(h));
            }
        }
        // ---- B tile: straight uint4 copy from preconverted weights ----
#pragma unroll
        for (int i = 0; i < 4; i++) {
            int u = tid + i * 256;              // 0..1023
            int buf = u >> 9;                   // 0 = hi, 1 = lo
            int rem = u & 511;
            int n = rem >> 2, c = rem & 3;      // 128 rows x 4 chunks of 16B
            const char* srcBase = buf ? (const char*)gW0l : (const char*)gW0h;
            uint4 v = *(const uint4*)(srcBase + n * 512 + kt * 64 + c * 16);
            char* dstBase = buf ? (char*)&Bl[n][0] : (char*)&Bh[n][0];
            *(uint4*)(dstBase + c * 16) = v;
        }
        __syncthreads();

#pragma unroll
        for (int ks = 0; ks < 2; ks++) {
            const uint32_t off = ks * 32;       // 16 bf16 = 32 bytes per k16 step
            uint32_t aH[2][4], aL[2][4];
#pragma unroll
            for (int mt = 0; mt < 2; mt++) {
                ldsm_x4(aH[mt][0], aH[mt][1], aH[mt][2], aH[mt][3], adAh[mt] + off);
                ldsm_x4(aL[mt][0], aL[mt][1], aL[mt][2], aL[mt][3], adAl[mt] + off);
            }
#pragma unroll
            for (int p = 0; p < 4; p++) {
                uint32_t bh0, bh1, bh2, bh3, bl0, bl1, bl2, bl3;
                ldsm_x4(bh0, bh1, bh2, bh3, adBh[p] + off);
                ldsm_x4(bl0, bl1, bl2, bl3, adBl[p] + off);
#pragma unroll
                for (int mt = 0; mt < 2; mt++) {
                    float* c0 = acc[mt][2 * p];
                    float* c1 = acc[mt][2 * p + 1];
                    mma_bf16(c0[0], c0[1], c0[2], c0[3],
                             aH[mt][0], aH[mt][1], aH[mt][2], aH[mt][3], bh0, bh1);
                    mma_bf16(c0[0], c0[1], c0[2], c0[3],
                             aH[mt][0], aH[mt][1], aH[mt][2], aH[mt][3], bl0, bl1);
                    mma_bf16(c0[0], c0[1], c0[2], c0[3],
                             aL[mt][0], aL[mt][1], aL[mt][2], aL[mt][3], bh0, bh1);
                    mma_bf16(c1[0], c1[1], c1[2], c1[3],
                             aH[mt][0], aH[mt][1], aH[mt][2], aH[mt][3], bh2, bh3);
                    mma_bf16(c1[0], c1[1], c1[2], c1[3],
                             aH[mt][0], aH[mt][1], aH[mt][2], aH[mt][3], bl2, bl3);
                    mma_bf16(c1[0], c1[1], c1[2], c1[3],
                             aL[mt][0], aL[mt][1], aL[mt][2], aL[mt][3], bh2, bh3);
                }
            }
        }
        __syncthreads();
    }

    // ---- epilogue: write z0 + fused attn0 (2 heads per warp) ----
    float pl[2][2][2], pr[2][2][2];
#pragma unroll
    for (int mt = 0; mt < 2; mt++)
#pragma unroll
        for (int hf = 0; hf < 2; hf++)
#pragma unroll
            for (int hl = 0; hl < 2; hl++) { pl[mt][hf][hl] = 0.f; pr[mt][hf][hl] = 0.f; }

#pragma unroll
    for (int mt = 0; mt < 2; mt++) {
        int r0 = rowBase + warp_m * 32 + mt * 16 + g;
        int c0 = warp_n * 64 + q * 2;
#pragma unroll
        for (int nt = 0; nt < 8; nt++) {
            float* c = acc[mt][nt];
            int col = c0 + nt * 8;
            int hl = nt >> 2;
            float a0c = al0[col], a1c = al0[col + 1];
            float r0c = ar0[col], r1c = ar0[col + 1];
            pl[mt][0][hl] += c[0] * a0c + c[1] * a1c;
            pr[mt][0][hl] += c[0] * r0c + c[1] * r1c;
            pl[mt][1][hl] += c[2] * a0c + c[3] * a1c;
            pr[mt][1][hl] += c[2] * r0c + c[3] * r1c;
            if (r0 < nrows)
                *(float2*)(g_z0 + (size_t)r0 * 128 + col) = make_float2(c[0], c[1]);
            if (r0 + 8 < nrows)
                *(float2*)(g_z0 + (size_t)(r0 + 8) * 128 + col) = make_float2(c[2], c[3]);
        }
    }
#pragma unroll
    for (int mt = 0; mt < 2; mt++)
#pragma unroll
        for (int hf = 0; hf < 2; hf++)
#pragma unroll
            for (int hl = 0; hl < 2; hl++) {
                float vl = pl[mt][hf][hl], vr = pr[mt][hf][hl];
                vl += __shfl_xor_sync(0xffffffffu, vl, 1);
                vl += __shfl_xor_sync(0xffffffffu, vl, 2);
                vr += __shfl_xor_sync(0xffffffffu, vr, 1);
                vr += __shfl_xor_sync(0xffffffffu, vr, 2);
                if (q == 0) {
                    int row = rowBase + warp_m * 32 + mt * 16 + hf * 8 + g;
                    if (row < nrows) {
                        int h = warp_n * 2 + hl;
                        g_el[row * 4 + h] = vl;
                        g_er[row * 4 + h] = vr;
                    }
                }
            }
}

// ================= gemm1: g_z1 = g_h0 @ W1 (+fused attn1) =================
#define G1_PAD 40
__global__ void __launch_bounds__(128) gemm1_mma_kernel(const float* __restrict__ al1,
                                                        const float* __restrict__ ar1,
                                                        int nrows) {
    __shared__ __nv_bfloat16 Ah[128][G1_PAD];
    __shared__ __nv_bfloat16 Al[128][G1_PAD];
    __shared__ __nv_bfloat16 Bh[40][G1_PAD];
    __shared__ __nv_bfloat16 Bl[40][G1_PAD];

    const int tid = threadIdx.x;
    const int lane = tid & 31;
    const int warp_m = tid >> 5;
    const int rowBase = blockIdx.x * 128;
    const int g = lane >> 2;
    const int q = lane & 3;

    float acc[2][5][4];
#pragma unroll
    for (int mt = 0; mt < 2; mt++)
#pragma unroll
        for (int nt = 0; nt < 5; nt++)
#pragma unroll
            for (int i = 0; i < 4; i++) acc[mt][nt][i] = 0.f;

    for (int kt = 0; kt < 4; kt++) {
#pragma unroll
        for (int i = 0; i < 8; i++) {
            int idx = tid + i * 128;
            int row = idx >> 3;
            int kq  = idx & 7;
            float4 v = make_float4(0.f, 0.f, 0.f, 0.f);
            if (rowBase + row < nrows)
                v = *(const float4*)(g_h0 + (size_t)(rowBase + row) * 128 + kt * 32 + kq * 4);
            int kl = kq * 4;
            const float vv[4] = {v.x, v.y, v.z, v.w};
#pragma unroll
            for (int j = 0; j < 4; j++) {
                __nv_bfloat16 h = __float2bfloat16_rn(vv[j]);
                Ah[row][kl + j] = h;
                Al[row][kl + j] = __float2bfloat16_rn(vv[j] - __bfloat162float(h));
            }
        }
#pragma unroll
        for (int i = 0; i < 3; i++) {
            int u = tid + i * 128;
            if (u < 320) {
                int buf = (u >= 160);
                int rem = u - buf * 160;
                int n = rem >> 2, c = rem & 3;
                const char* srcBase = buf ? (const char*)gW1l : (const char*)gW1h;
                uint4 v = *(const uint4*)(srcBase + n * 256 + kt * 64 + c * 16);
                char* dstBase = buf ? (char*)&Bl[n][0] : (char*)&Bh[n][0];
                *(uint4*)(dstBase + c * 16) = v;
            }
        }
        __syncthreads();

#pragma unroll
        for (int ks = 0; ks < 2; ks++) {
            const int w0 = ks * 8 + q;
            uint32_t aH[2][4], aL[2][4];
#pragma unroll
            for (int mt = 0; mt < 2; mt++) {
                int r0 = warp_m * 32 + mt * 16 + g;
                const uint32_t* ph0 = (const uint32_t*)&Ah[r0][0];
                const uint32_t* ph8 = (const uint32_t*)&Ah[r0 + 8][0];
                const uint32_t* pl0 = (const uint32_t*)&Al[r0][0];
                const uint32_t* pl8 = (const uint32_t*)&Al[r0 + 8][0];
                aH[mt][0] = ph0[w0]; aH[mt][1] = ph8[w0];
                aH[mt][2] = ph0[w0 + 4]; aH[mt][3] = ph8[w0 + 4];
                aL[mt][0] = pl0[w0]; aL[mt][1] = pl8[w0];
                aL[mt][2] = pl0[w0 + 4]; aL[mt][3] = pl8[w0 + 4];
            }
#pragma unroll
            for (int nt = 0; nt < 5; nt++) {
                int n0 = nt * 8 + g;
                const uint32_t* pbh = (const uint32_t*)&Bh[n0][0];
                const uint32_t* pbl = (const uint32_t*)&Bl[n0][0];
                uint32_t bH0 = pbh[w0], bH1 = pbh[w0 + 4];
                uint32_t bL0 = pbl[w0], bL1 = pbl[w0 + 4];
#pragma unroll
                for (int mt = 0; mt < 2; mt++) {
                    float* c = acc[mt][nt];
                    mma_bf16(c[0], c[1], c[2], c[3],
                             aH[mt][0], aH[mt][1], aH[mt][2], aH[mt][3], bH0, bH1);
                    mma_bf16(c[0], c[1], c[2], c[3],
                             aH[mt][0], aH[mt][1], aH[mt][2], aH[mt][3], bL0, bL1);
                    mma_bf16(c[0], c[1], c[2], c[3],
                             aL[mt][0], aL[mt][1], aL[mt][2], aL[mt][3], bH0, bH1);
                }
            }
        }
        __syncthreads();
    }

    float pl[2][2], pr[2][2];
#pragma unroll
    for (int mt = 0; mt < 2; mt++)
#pragma unroll
        for (int hf = 0; hf < 2; hf++) { pl[mt][hf] = 0.f; pr[mt][hf] = 0.f; }

#pragma unroll
    for (int mt = 0; mt < 2; mt++) {
        int r0 = rowBase + warp_m * 32 + mt * 16 + g;
#pragma unroll
        for (int nt = 0; nt < 5; nt++) {
            float* c = acc[mt][nt];
            int col = nt * 8 + q * 2;
            float a0c = al1[col], a1c = al1[col + 1];
            float r0c = ar1[col], r1c = ar1[col + 1];
            pl[mt][0] += c[0] * a0c + c[1] * a1c;
            pr[mt][0] += c[0] * r0c + c[1] * r1c;
            pl[mt][1] += c[2] * a0c + c[3] * a1c;
            pr[mt][1] += c[2] * r0c + c[3] * r1c;
            if (r0 < nrows)
                *(float2*)(g_z1 + (size_t)r0 * 40 + col) = make_float2(c[0], c[1]);
            if (r0 + 8 < nrows)
                *(float2*)(g_z1 + (size_t)(r0 + 8) * 40 + col) = make_float2(c[2], c[3]);
        }
    }
#pragma unroll
    for (int mt = 0; mt < 2; mt++)
#pragma unroll
        for (int hf = 0; hf < 2; hf++) {
            float vl = pl[mt][hf], vr = pr[mt][hf];
            vl += __shfl_xor_sync(0xffffffffu, vl, 1);
            vl += __shfl_xor_sync(0xffffffffu, vl, 2);
            vr += __shfl_xor_sync(0xffffffffu, vr, 1);
            vr += __shfl_xor_sync(0xffffffffu, vr, 2);
            if (q == 0) {
                int row = rowBase + warp_m * 32 + mt * 16 + hf * 8 + g;
                if (row < nrows) { g_el[row] = vl; g_er[row] = vr; }
            }
        }
}

// ---------------- CSR: count ----------------
__global__ void csr_count_kernel(const int* __restrict__ src, const int* __restrict__ dst, int E) {
    int i = blockIdx.x * blockDim.x + threadIdx.x;
    int EP = E + NN;
    if (i >= EP) return;
    int d;
    if (i < E) {
        int s = src[i];
        d = dst[i];
        if (s == d) return;
    } else {
        d = i - E;
    }
    g_epos[i] = atomicAdd(&g_cnt[d], 1);
}

// ---------------- scanall: single-kernel exclusive scan of g_cnt -> g_rowptr ----------------
__global__ void scanall_kernel() {
    __shared__ int sh[512];
    __shared__ int swr[16];
    __shared__ int s_off;
    const int base = blockIdx.x * 512;

    int off = 0;
    for (int i = threadIdx.x; i < base; i += 512) off += g_cnt[i];
#pragma unroll
    for (int o = 16; o > 0; o >>= 1) off += __shfl_xor_sync(0xffffffffu, off, o);
    if ((threadIdx.x & 31) == 0) swr[threadIdx.x >> 5] = off;
    __syncthreads();
    if (threadIdx.x == 0) {
        int t = 0;
#pragma unroll
        for (int i = 0; i < 16; i++) t += swr[i];
        s_off = t;
    }
    __syncthreads();
    off = s_off;

    int i = base + threadIdx.x;
    int v = (i < NN) ? g_cnt[i] : 0;
    sh[threadIdx.x] = v;
    __syncthreads();
    for (int o = 1; o < 512; o <<= 1) {
        int t = (threadIdx.x >= o) ? sh[threadIdx.x - o] : 0;
        __syncthreads();
        sh[threadIdx.x] += t;
        __syncthreads();
    }
    if (i < NN) g_rowptr[i] = sh[threadIdx.x] - v + off;
}

// ---------------- scatter: atomic-free via g_epos ----------------
__global__ void csr_scatter_kernel(const int* __restrict__ src, const int* __restrict__ dst, int E) {
    int i = blockIdx.x * blockDim.x + threadIdx.x;
    int EP = E + NN;
    if (i >= EP) return;
    int s, d;
    if (i < E) {
        s = src[i]; d = dst[i];
        if (s == d) return;
    } else {
        s = d = i - E;
    }
    g_srcs[g_rowptr[d] + g_epos[i]] = s;
}

// ---------------- layer0 gather: warp/node, shift-free clamped softmax ----------------
__device__ __forceinline__ float lrelu_clamp(float e) {
    e = e > 0.f ? e : NEG_SLOPE * e;
    return fminf(fmaxf(e, -80.f), 80.f);
}

__global__ void __launch_bounds__(256) gather0_kernel(const float* __restrict__ b0) {
    __shared__ float4 sal[8][32];
    __shared__ int    ssrc[8][32];
    int w = (blockIdx.x * blockDim.x + threadIdx.x) >> 5;
    int lane = threadIdx.x & 31;
    int wl = (threadIdx.x >> 5);
    if (w >= NN) return;
    const int beg = g_rowptr[w];
    const int deg = g_cnt[w];
    const float4 erd = *(const float4*)(g_er + w * 4);

    float s0 = 0.f, s1 = 0.f, s2 = 0.f, s3 = 0.f;
    for (int t = lane; t < deg; t += 32) {
        int s = g_srcs[beg + t];
        float4 el = *(const float4*)(g_el + s * 4);
        s0 += __expf(lrelu_clamp(el.x + erd.x));
        s1 += __expf(lrelu_clamp(el.y + erd.y));
        s2 += __expf(lrelu_clamp(el.z + erd.z));
        s3 += __expf(lrelu_clamp(el.w + erd.w));
    }
#pragma unroll
    for (int o = 16; o > 0; o >>= 1) {
        s0 += __shfl_xor_sync(0xffffffffu, s0, o);
        s1 += __shfl_xor_sync(0xffffffffu, s1, o);
        s2 += __shfl_xor_sync(0xffffffffu, s2, o);
        s3 += __shfl_xor_sync(0xffffffffu, s3, o);
    }
    const float i0 = __frcp_rn(s0), i1 = __frcp_rn(s1), i2 = __frcp_rn(s2), i3 = __frcp_rn(s3);

    float a0 = 0.f, a1 = 0.f, a2 = 0.f, a3 = 0.f;
    for (int c0 = 0; c0 < deg; c0 += 32) {
        int t = c0 + lane;
        float4 av = make_float4(0.f, 0.f, 0.f, 0.f);
        int sidx = 0;
        if (t < deg) {
            sidx = g_srcs[beg + t];
            float4 el = *(const float4*)(g_el + sidx * 4);
            av = make_float4(__expf(lrelu_clamp(el.x + erd.x)) * i0,
                             __expf(lrelu_clamp(el.y + erd.y)) * i1,
                             __expf(lrelu_clamp(el.z + erd.z)) * i2,
                             __expf(lrelu_clamp(el.w + erd.w)) * i3);
        }
        sal[wl][lane] = av;
        ssrc[wl][lane] = sidx;
        __syncwarp();
        int lim = min(32, deg - c0);
        for (int j = 0; j < lim; j++) {
            float4 aj = sal[wl][j];
            const float* zr = g_z0 + (size_t)ssrc[wl][j] * 128;
            a0 = fmaf(aj.x, zr[lane],      a0);
            a1 = fmaf(aj.y, zr[32 + lane], a1);
            a2 = fmaf(aj.z, zr[64 + lane], a2);
            a3 = fmaf(aj.w, zr[96 + lane], a3);
        }
        __syncwarp();
    }
    float* hr = g_h0 + (size_t)w * 128;
    float v;
    v = a0 + b0[lane];       hr[lane]      = v > 0.f ? v : (__expf(v) - 1.f);
    v = a1 + b0[32 + lane];  hr[32 + lane] = v > 0.f ? v : (__expf(v) - 1.f);
    v = a2 + b0[64 + lane];  hr[64 + lane] = v > 0.f ? v : (__expf(v) - 1.f);
    v = a3 + b0[96 + lane];  hr[96 + lane] = v > 0.f ? v : (__expf(v) - 1.f);
}

// ---------------- layer1 gather (+ zero g_cnt for next call) ----------------
__global__ void __launch_bounds__(256) gather1_kernel(float* __restrict__ out,
                                                      const float* __restrict__ b1) {
    __shared__ float sal[8][32];
    __shared__ int   ssrc[8][32];
    int w = (blockIdx.x * blockDim.x + threadIdx.x) >> 5;
    int lane = threadIdx.x & 31;
    int wl = (threadIdx.x >> 5);
    if (w >= NN) return;
    const int beg = g_rowptr[w];
    const int deg = g_cnt[w];
    const float erd = g_er[w];

    float ssum = 0.f;
    for (int t = lane; t < deg; t += 32) {
        int s = g_srcs[beg + t];
        ssum += __expf(lrelu_clamp(g_el[s] + erd));
    }
#pragma unroll
    for (int o = 16; o > 0; o >>= 1) ssum += __shfl_xor_sync(0xffffffffu, ssum, o);
    const float inv = __frcp_rn(ssum);

    float a0 = 0.f, a1 = 0.f;
    for (int c0 = 0; c0 < deg; c0 += 32) {
        int t = c0 + lane;
        float av = 0.f;
        int sidx = 0;
        if (t < deg) {
            sidx = g_srcs[beg + t];
            av = __expf(lrelu_clamp(g_el[sidx] + erd)) * inv;
        }
        sal[wl][lane] = av;
        ssrc[wl][lane] = sidx;
        __syncwarp();
        int lim = min(32, deg - c0);
        for (int j = 0; j < lim; j++) {
            float aj = sal[wl][j];
            const float* zr = g_z1 + (size_t)ssrc[wl][j] * 40;
            a0 = fmaf(aj, zr[lane], a0);
            if (lane < 8) a1 = fmaf(aj, zr[32 + lane], a1);
        }
        __syncwarp();
    }
    float v = a0 + b1[lane];
    out[(size_t)w * 40 + lane] = v > 0.f ? v : (__expf(v) - 1.f);
    if (lane < 8) {
        v = a1 + b1[32 + lane];
        out[(size_t)w * 40 + 32 + lane] = v > 0.f ? v : (__expf(v) - 1.f);
    }
    __syncwarp();
    if (lane == 0) g_cnt[w] = 0;   // restore all-zero invariant for next call
}

// ---------------- launch ----------------
extern "C" void kernel_launch(void* const* d_in, const int* in_sizes, int n_in,
                              void* d_out, int out_size) {
    const float* x   = (const float*)d_in[0];
    const int*   src = (const int*)d_in[1];
    const int*   dst = (const int*)d_in[2];
    const float* W0  = (const float*)d_in[3];
    const float* al0 = (const float*)d_in[4];
    const float* ar0 = (const float*)d_in[5];
    const float* b0  = (const float*)d_in[6];
    const float* W1  = (const float*)d_in[7];
    const float* al1 = (const float*)d_in[8];
    const float* ar1 = (const float*)d_in[9];
    const float* b1  = (const float*)d_in[10];
    float* out = (float*)d_out;

    const int E  = in_sizes[1];
    const int EP = E + NN;

    csr_count_kernel<<<(EP + 255) / 256, 256>>>(src, dst, E);          // 0
    scanall_kernel<<<NB_SCAN, 512>>>();                                // 1
    wconv_kernel<<<(128 * 256 + 128 * 40 + 255) / 256, 256>>>(W0, W1); // 2
    gemm0_mma_kernel<<<(NN + 127) / 128, 256>>>(x, al0, ar0, NN);      // 3 <- profiled
    csr_scatter_kernel<<<(EP + 255) / 256, 256>>>(src, dst, E);        // 4
    gather0_kernel<<<(NN * 32 + 255) / 256, 256>>>(b0);                // 5
    gemm1_mma_kernel<<<(NN + 127) / 128, 128>>>(al1, ar1, NN);         // 6
    gather1_kernel<<<(NN * 32 + 255) / 256, 256>>>(out, b1);           // 7
}

// round 14
// speedup vs baseline: 1.1420x; 1.1420x over previous
#include <cuda_runtime.h>
#include <cuda_bf16.h>
#include <cstdint>

#define NN 50000
#define EPMAX 850000
#define NEG_SLOPE 0.2f
#define NB_SCAN 98    // ceil(50000/512)

// ---------------- scratch (device globals; no allocation allowed) ----------------
__device__ __align__(16) float g_z0[NN * 128];
__device__ __align__(16) float g_h0[NN * 128];
__device__ __align__(16) float g_z1[NN * 40];
__device__ __align__(16) float g_el[NN * 4];
__device__ __align__(16) float g_er[NN * 4];
__device__ int g_cnt[NN];      // in-degree; all-zero at entry of every call (invariant)
__device__ int g_rowptr[NN];
__device__ int g_srcs[EPMAX];
__device__ int g_epos[EPMAX];  // per-edge position within destination segment
// preconverted weights (bf16 hi/lo, transposed to [n][k])
__device__ __align__(16) __nv_bfloat16 gW0h[128 * 256];
__device__ __align__(16) __nv_bfloat16 gW0l[128 * 256];
__device__ __align__(16) __nv_bfloat16 gW1h[40 * 128];
__device__ __align__(16) __nv_bfloat16 gW1l[40 * 128];

// ================= split-bf16 MMA helper =================
__device__ __forceinline__ void mma_bf16(float& c0, float& c1, float& c2, float& c3,
                                         uint32_t a0, uint32_t a1, uint32_t a2, uint32_t a3,
                                         uint32_t b0, uint32_t b1) {
    asm volatile(
        "mma.sync.aligned.m16n8k16.row.col.f32.bf16.bf16.f32 "
        "{%0,%1,%2,%3}, {%4,%5,%6,%7}, {%8,%9}, {%0,%1,%2,%3};"
        : "+f"(c0), "+f"(c1), "+f"(c2), "+f"(c3)
        : "r"(a0), "r"(a1), "r"(a2), "r"(a3), "r"(b0), "r"(b1));
}

// ================= wconv: one-time weight split (W0 and W1) =================
__global__ void wconv_kernel(const float* __restrict__ W0, const float* __restrict__ W1) {
    int i = blockIdx.x * blockDim.x + threadIdx.x;
    if (i < 128 * 256) {
        int k = i >> 7, n = i & 127;          // W0[k][n], k<256
        float v = W0[k * 128 + n];
        __nv_bfloat16 h = __float2bfloat16_rn(v);
        gW0h[n * 256 + k] = h;
        gW0l[n * 256 + k] = __float2bfloat16_rn(v - __bfloat162float(h));
    } else if (i < 128 * 256 + 128 * 40) {
        int j = i - 128 * 256;
        int k = j / 40, n = j % 40;           // W1[k][n], k<128
        float v = W1[k * 40 + n];
        __nv_bfloat16 h = __float2bfloat16_rn(v);
        gW1h[n * 128 + k] = h;
        gW1l[n * 128 + k] = __float2bfloat16_rn(v - __bfloat162float(h));
    }
}

// ================= gemm0: g_z0 = x @ W0 (+fused attn0), BM=128 (R10 config) =================
#define G0_K 256
#define G0_PAD 40

__global__ void __launch_bounds__(256) gemm0_mma_kernel(const float* __restrict__ A,
                                                        const float* __restrict__ al0,
                                                        const float* __restrict__ ar0,
                                                        int nrows) {
    __shared__ __nv_bfloat16 Ah[128][G0_PAD];
    __shared__ __nv_bfloat16 Al[128][G0_PAD];
    __shared__ __nv_bfloat16 Bh[128][G0_PAD];   // [n][k'] tile
    __shared__ __nv_bfloat16 Bl[128][G0_PAD];

    const int tid = threadIdx.x;
    const int lane = tid & 31;
    const int wid = tid >> 5;
    const int warp_m = wid & 3;
    const int warp_n = wid >> 2;
    const int rowBase = blockIdx.x * 128;
    const int g = lane >> 2;
    const int q = lane & 3;

    float acc[2][8][4];
#pragma unroll
    for (int mt = 0; mt < 2; mt++)
#pragma unroll
        for (int nt = 0; nt < 8; nt++)
#pragma unroll
            for (int i = 0; i < 4; i++) acc[mt][nt][i] = 0.f;

    for (int kt = 0; kt < G0_K / 32; kt++) {
        // ---- A tile 128x32 fp32 -> bf16 hi/lo ----
#pragma unroll
        for (int i = 0; i < 4; i++) {
            int idx = tid + i * 256;
            int row = idx >> 3;
            int kq  = idx & 7;
            float4 v = make_float4(0.f, 0.f, 0.f, 0.f);
            if (rowBase + row < nrows)
                v = *(const float4*)(A + (size_t)(rowBase + row) * G0_K + kt * 32 + kq * 4);
            int kl = kq * 4;
            const float vv[4] = {v.x, v.y, v.z, v.w};
#pragma unroll
            for (int j = 0; j < 4; j++) {
                __nv_bfloat16 h = __float2bfloat16_rn(vv[j]);
                Ah[row][kl + j] = h;
                Al[row][kl + j] = __float2bfloat16_rn(vv[j] - __bfloat162float(h));
            }
        }
        // ---- B tile: straight uint4 copy from preconverted weights ----
#pragma unroll
        for (int i = 0; i < 4; i++) {
            int u = tid + i * 256;              // 0..1023
            int buf = u >> 9;                   // 0 = hi, 1 = lo
            int rem = u & 511;
            int n = rem >> 2, c = rem & 3;      // 128 rows x 4 chunks of 16B
            const char* srcBase = buf ? (const char*)gW0l : (const char*)gW0h;
            uint4 v = *(const uint4*)(srcBase + n * 512 + kt * 64 + c * 16);
            char* dstBase = buf ? (char*)&Bl[n][0] : (char*)&Bh[n][0];
            *(uint4*)(dstBase + c * 16) = v;
        }
        __syncthreads();

#pragma unroll
        for (int ks = 0; ks < 2; ks++) {
            const int w0 = ks * 8 + q;
            uint32_t aH[2][4], aL[2][4];
#pragma unroll
            for (int mt = 0; mt < 2; mt++) {
                int r0 = warp_m * 32 + mt * 16 + g;
                const uint32_t* ph0 = (const uint32_t*)&Ah[r0][0];
                const uint32_t* ph8 = (const uint32_t*)&Ah[r0 + 8][0];
                const uint32_t* pl0 = (const uint32_t*)&Al[r0][0];
                const uint32_t* pl8 = (const uint32_t*)&Al[r0 + 8][0];
                aH[mt][0] = ph0[w0]; aH[mt][1] = ph8[w0];
                aH[mt][2] = ph0[w0 + 4]; aH[mt][3] = ph8[w0 + 4];
                aL[mt][0] = pl0[w0]; aL[mt][1] = pl8[w0];
                aL[mt][2] = pl0[w0 + 4]; aL[mt][3] = pl8[w0 + 4];
            }
#pragma unroll
            for (int nt = 0; nt < 8; nt++) {
                int n0 = warp_n * 64 + nt * 8 + g;
                const uint32_t* pbh = (const uint32_t*)&Bh[n0][0];
                const uint32_t* pbl = (const uint32_t*)&Bl[n0][0];
                uint32_t bH0 = pbh[w0], bH1 = pbh[w0 + 4];
                uint32_t bL0 = pbl[w0], bL1 = pbl[w0 + 4];
#pragma unroll
                for (int mt = 0; mt < 2; mt++) {
                    float* c = acc[mt][nt];
                    mma_bf16(c[0], c[1], c[2], c[3],
                             aH[mt][0], aH[mt][1], aH[mt][2], aH[mt][3], bH0, bH1);
                    mma_bf16(c[0], c[1], c[2], c[3],
                             aH[mt][0], aH[mt][1], aH[mt][2], aH[mt][3], bL0, bL1);
                    mma_bf16(c[0], c[1], c[2], c[3],
                             aL[mt][0], aL[mt][1], aL[mt][2], aL[mt][3], bH0, bH1);
                }
            }
        }
        __syncthreads();
    }

    float pl[2][2][2], pr[2][2][2];
#pragma unroll
    for (int mt = 0; mt < 2; mt++)
#pragma unroll
        for (int hf = 0; hf < 2; hf++)
#pragma unroll
            for (int hl = 0; hl < 2; hl++) { pl[mt][hf][hl] = 0.f; pr[mt][hf][hl] = 0.f; }

#pragma unroll
    for (int mt = 0; mt < 2; mt++) {
        int r0 = rowBase + warp_m * 32 + mt * 16 + g;
        int c0 = warp_n * 64 + q * 2;
#pragma unroll
        for (int nt = 0; nt < 8; nt++) {
            float* c = acc[mt][nt];
            int col = c0 + nt * 8;
            int hl = nt >> 2;
            float a0c = al0[col], a1c = al0[col + 1];
            float r0c = ar0[col], r1c = ar0[col + 1];
            pl[mt][0][hl] += c[0] * a0c + c[1] * a1c;
            pr[mt][0][hl] += c[0] * r0c + c[1] * r1c;
            pl[mt][1][hl] += c[2] * a0c + c[3] * a1c;
            pr[mt][1][hl] += c[2] * r0c + c[3] * r1c;
            if (r0 < nrows)
                *(float2*)(g_z0 + (size_t)r0 * 128 + col) = make_float2(c[0], c[1]);
            if (r0 + 8 < nrows)
                *(float2*)(g_z0 + (size_t)(r0 + 8) * 128 + col) = make_float2(c[2], c[3]);
        }
    }
#pragma unroll
    for (int mt = 0; mt < 2; mt++)
#pragma unroll
        for (int hf = 0; hf < 2; hf++)
#pragma unroll
            for (int hl = 0; hl < 2; hl++) {
                float vl = pl[mt][hf][hl], vr = pr[mt][hf][hl];
                vl += __shfl_xor_sync(0xffffffffu, vl, 1);
                vl += __shfl_xor_sync(0xffffffffu, vl, 2);
                vr += __shfl_xor_sync(0xffffffffu, vr, 1);
                vr += __shfl_xor_sync(0xffffffffu, vr, 2);
                if (q == 0) {
                    int row = rowBase + warp_m * 32 + mt * 16 + hf * 8 + g;
                    if (row < nrows) {
                        int h = warp_n * 2 + hl;
                        g_el[row * 4 + h] = vl;
                        g_er[row * 4 + h] = vr;
                    }
                }
            }
}

// ================= gemm1: g_z1 = g_h0 @ W1 (+fused attn1) =================
#define G1_PAD 40
__global__ void __launch_bounds__(128) gemm1_mma_kernel(const float* __restrict__ al1,
                                                        const float* __restrict__ ar1,
                                                        int nrows) {
    __shared__ __nv_bfloat16 Ah[128][G1_PAD];
    __shared__ __nv_bfloat16 Al[128][G1_PAD];
    __shared__ __nv_bfloat16 Bh[40][G1_PAD];
    __shared__ __nv_bfloat16 Bl[40][G1_PAD];

    const int tid = threadIdx.x;
    const int lane = tid & 31;
    const int warp_m = tid >> 5;
    const int rowBase = blockIdx.x * 128;
    const int g = lane >> 2;
    const int q = lane & 3;

    float acc[2][5][4];
#pragma unroll
    for (int mt = 0; mt < 2; mt++)
#pragma unroll
        for (int nt = 0; nt < 5; nt++)
#pragma unroll
            for (int i = 0; i < 4; i++) acc[mt][nt][i] = 0.f;

    for (int kt = 0; kt < 4; kt++) {
#pragma unroll
        for (int i = 0; i < 8; i++) {
            int idx = tid + i * 128;
            int row = idx >> 3;
            int kq  = idx & 7;
            float4 v = make_float4(0.f, 0.f, 0.f, 0.f);
            if (rowBase + row < nrows)
                v = *(const float4*)(g_h0 + (size_t)(rowBase + row) * 128 + kt * 32 + kq * 4);
            int kl = kq * 4;
            const float vv[4] = {v.x, v.y, v.z, v.w};
#pragma unroll
            for (int j = 0; j < 4; j++) {
                __nv_bfloat16 h = __float2bfloat16_rn(vv[j]);
                Ah[row][kl + j] = h;
                Al[row][kl + j] = __float2bfloat16_rn(vv[j] - __bfloat162float(h));
            }
        }
#pragma unroll
        for (int i = 0; i < 3; i++) {
            int u = tid + i * 128;
            if (u < 320) {
                int buf = (u >= 160);
                int rem = u - buf * 160;
                int n = rem >> 2, c = rem & 3;
                const char* srcBase = buf ? (const char*)gW1l : (const char*)gW1h;
                uint4 v = *(const uint4*)(srcBase + n * 256 + kt * 64 + c * 16);
                char* dstBase = buf ? (char*)&Bl[n][0] : (char*)&Bh[n][0];
                *(uint4*)(dstBase + c * 16) = v;
            }
        }
        __syncthreads();

#pragma unroll
        for (int ks = 0; ks < 2; ks++) {
            const int w0 = ks * 8 + q;
            uint32_t aH[2][4], aL[2][4];
#pragma unroll
            for (int mt = 0; mt < 2; mt++) {
                int r0 = warp_m * 32 + mt * 16 + g;
                const uint32_t* ph0 = (const uint32_t*)&Ah[r0][0];
                const uint32_t* ph8 = (const uint32_t*)&Ah[r0 + 8][0];
                const uint32_t* pl0 = (const uint32_t*)&Al[r0][0];
                const uint32_t* pl8 = (const uint32_t*)&Al[r0 + 8][0];
                aH[mt][0] = ph0[w0]; aH[mt][1] = ph8[w0];
                aH[mt][2] = ph0[w0 + 4]; aH[mt][3] = ph8[w0 + 4];
                aL[mt][0] = pl0[w0]; aL[mt][1] = pl8[w0];
                aL[mt][2] = pl0[w0 + 4]; aL[mt][3] = pl8[w0 + 4];
            }
#pragma unroll
            for (int nt = 0; nt < 5; nt++) {
                int n0 = nt * 8 + g;
                const uint32_t* pbh = (const uint32_t*)&Bh[n0][0];
                const uint32_t* pbl = (const uint32_t*)&Bl[n0][0];
                uint32_t bH0 = pbh[w0], bH1 = pbh[w0 + 4];
                uint32_t bL0 = pbl[w0], bL1 = pbl[w0 + 4];
#pragma unroll
                for (int mt = 0; mt < 2; mt++) {
                    float* c = acc[mt][nt];
                    mma_bf16(c[0], c[1], c[2], c[3],
                             aH[mt][0], aH[mt][1], aH[mt][2], aH[mt][3], bH0, bH1);
                    mma_bf16(c[0], c[1], c[2], c[3],
                             aH[mt][0], aH[mt][1], aH[mt][2], aH[mt][3], bL0, bL1);
                    mma_bf16(c[0], c[1], c[2], c[3],
                             aL[mt][0], aL[mt][1], aL[mt][2], aL[mt][3], bH0, bH1);
                }
            }
        }
        __syncthreads();
    }

    float pl[2][2], pr[2][2];
#pragma unroll
    for (int mt = 0; mt < 2; mt++)
#pragma unroll
        for (int hf = 0; hf < 2; hf++) { pl[mt][hf] = 0.f; pr[mt][hf] = 0.f; }

#pragma unroll
    for (int mt = 0; mt < 2; mt++) {
        int r0 = rowBase + warp_m * 32 + mt * 16 + g;
#pragma unroll
        for (int nt = 0; nt < 5; nt++) {
            float* c = acc[mt][nt];
            int col = nt * 8 + q * 2;
            float a0c = al1[col], a1c = al1[col + 1];
            float r0c = ar1[col], r1c = ar1[col + 1];
            pl[mt][0] += c[0] * a0c + c[1] * a1c;
            pr[mt][0] += c[0] * r0c + c[1] * r1c;
            pl[mt][1] += c[2] * a0c + c[3] * a1c;
            pr[mt][1] += c[2] * r0c + c[3] * r1c;
            if (r0 < nrows)
                *(float2*)(g_z1 + (size_t)r0 * 40 + col) = make_float2(c[0], c[1]);
            if (r0 + 8 < nrows)
                *(float2*)(g_z1 + (size_t)(r0 + 8) * 40 + col) = make_float2(c[2], c[3]);
        }
    }
#pragma unroll
    for (int mt = 0; mt < 2; mt++)
#pragma unroll
        for (int hf = 0; hf < 2; hf++) {
            float vl = pl[mt][hf], vr = pr[mt][hf];
            vl += __shfl_xor_sync(0xffffffffu, vl, 1);
            vl += __shfl_xor_sync(0xffffffffu, vl, 2);
            vr += __shfl_xor_sync(0xffffffffu, vr, 1);
            vr += __shfl_xor_sync(0xffffffffu, vr, 2);
            if (q == 0) {
                int row = rowBase + warp_m * 32 + mt * 16 + hf * 8 + g;
                if (row < nrows) { g_el[row] = vl; g_er[row] = vr; }
            }
        }
}

// ---------------- CSR: count ----------------
__global__ void csr_count_kernel(const int* __restrict__ src, const int* __restrict__ dst, int E) {
    int i = blockIdx.x * blockDim.x + threadIdx.x;
    int EP = E + NN;
    if (i >= EP) return;
    int d;
    if (i < E) {
        int s = src[i];
        d = dst[i];
        if (s == d) return;
    } else {
        d = i - E;
    }
    g_epos[i] = atomicAdd(&g_cnt[d], 1);
}

// ---------------- scanall: single-kernel exclusive scan of g_cnt -> g_rowptr ----------------
__global__ void scanall_kernel() {
    __shared__ int sh[512];
    __shared__ int swr[16];
    __shared__ int s_off;
    const int base = blockIdx.x * 512;

    int off = 0;
    for (int i = threadIdx.x; i < base; i += 512) off += g_cnt[i];
#pragma unroll
    for (int o = 16; o > 0; o >>= 1) off += __shfl_xor_sync(0xffffffffu, off, o);
    if ((threadIdx.x & 31) == 0) swr[threadIdx.x >> 5] = off;
    __syncthreads();
    if (threadIdx.x == 0) {
        int t = 0;
#pragma unroll
        for (int i = 0; i < 16; i++) t += swr[i];
        s_off = t;
    }
    __syncthreads();
    off = s_off;

    int i = base + threadIdx.x;
    int v = (i < NN) ? g_cnt[i] : 0;
    sh[threadIdx.x] = v;
    __syncthreads();
    for (int o = 1; o < 512; o <<= 1) {
        int t = (threadIdx.x >= o) ? sh[threadIdx.x - o] : 0;
        __syncthreads();
        sh[threadIdx.x] += t;
        __syncthreads();
    }
    if (i < NN) g_rowptr[i] = sh[threadIdx.x] - v + off;
}

// ---------------- scatter: atomic-free via g_epos ----------------
__global__ void csr_scatter_kernel(const int* __restrict__ src, const int* __restrict__ dst, int E) {
    int i = blockIdx.x * blockDim.x + threadIdx.x;
    int EP = E + NN;
    if (i >= EP) return;
    int s, d;
    if (i < E) {
        s = src[i]; d = dst[i];
        if (s == d) return;
    } else {
        s = d = i - E;
    }
    g_srcs[g_rowptr[d] + g_epos[i]] = s;
}

// ---------------- layer0 gather: warp/node, shift-free clamped softmax ----------------
__device__ __forceinline__ float lrelu_clamp(float e) {
    e = e > 0.f ? e : NEG_SLOPE * e;
    return fminf(fmaxf(e, -80.f), 80.f);
}

__global__ void __launch_bounds__(256) gather0_kernel(const float* __restrict__ b0) {
    __shared__ float4 sal[8][32];
    __shared__ int    ssrc[8][32];
    int w = (blockIdx.x * blockDim.x + threadIdx.x) >> 5;
    int lane = threadIdx.x & 31;
    int wl = (threadIdx.x >> 5);
    if (w >= NN) return;
    const int beg = g_rowptr[w];
    const int deg = g_cnt[w];
    const float4 erd = *(const float4*)(g_er + w * 4);

    float s0 = 0.f, s1 = 0.f, s2 = 0.f, s3 = 0.f;
    for (int t = lane; t < deg; t += 32) {
        int s = g_srcs[beg + t];
        float4 el = *(const float4*)(g_el + s * 4);
        s0 += __expf(lrelu_clamp(el.x + erd.x));
        s1 += __expf(lrelu_clamp(el.y + erd.y));
        s2 += __expf(lrelu_clamp(el.z + erd.z));
        s3 += __expf(lrelu_clamp(el.w + erd.w));
    }
#pragma unroll
    for (int o = 16; o > 0; o >>= 1) {
        s0 += __shfl_xor_sync(0xffffffffu, s0, o);
        s1 += __shfl_xor_sync(0xffffffffu, s1, o);
        s2 += __shfl_xor_sync(0xffffffffu, s2, o);
        s3 += __shfl_xor_sync(0xffffffffu, s3, o);
    }
    const float i0 = __frcp_rn(s0), i1 = __frcp_rn(s1), i2 = __frcp_rn(s2), i3 = __frcp_rn(s3);

    float a0 = 0.f, a1 = 0.f, a2 = 0.f, a3 = 0.f;
    for (int c0 = 0; c0 < deg; c0 += 32) {
        int t = c0 + lane;
        float4 av = make_float4(0.f, 0.f, 0.f, 0.f);
        int sidx = 0;
        if (t < deg) {
            sidx = g_srcs[beg + t];
            float4 el = *(const float4*)(g_el + sidx * 4);
            av = make_float4(__expf(lrelu_clamp(el.x + erd.x)) * i0,
                             __expf(lrelu_clamp(el.y + erd.y)) * i1,
                             __expf(lrelu_clamp(el.z + erd.z)) * i2,
                             __expf(lrelu_clamp(el.w + erd.w)) * i3);
        }
        sal[wl][lane] = av;
        ssrc[wl][lane] = sidx;
        __syncwarp();
        int lim = min(32, deg - c0);
        for (int j = 0; j < lim; j++) {
            float4 aj = sal[wl][j];
            const float* zr = g_z0 + (size_t)ssrc[wl][j] * 128;
            a0 = fmaf(aj.x, zr[lane],      a0);
            a1 = fmaf(aj.y, zr[32 + lane], a1);
            a2 = fmaf(aj.z, zr[64 + lane], a2);
            a3 = fmaf(aj.w, zr[96 + lane], a3);
        }
        __syncwarp();
    }
    float* hr = g_h0 + (size_t)w * 128;
    float v;
    v = a0 + b0[lane];       hr[lane]      = v > 0.f ? v : (__expf(v) - 1.f);
    v = a1 + b0[32 + lane];  hr[32 + lane] = v > 0.f ? v : (__expf(v) - 1.f);
    v = a2 + b0[64 + lane];  hr[64 + lane] = v > 0.f ? v : (__expf(v) - 1.f);
    v = a3 + b0[96 + lane];  hr[96 + lane] = v > 0.f ? v : (__expf(v) - 1.f);
}

// ---------------- layer1 gather (+ zero g_cnt for next call) ----------------
__global__ void __launch_bounds__(256) gather1_kernel(float* __restrict__ out,
                                                      const float* __restrict__ b1) {
    __shared__ float sal[8][32];
    __shared__ int   ssrc[8][32];
    int w = (blockIdx.x * blockDim.x + threadIdx.x) >> 5;
    int lane = threadIdx.x & 31;
    int wl = (threadIdx.x >> 5);
    if (w >= NN) return;
    const int beg = g_rowptr[w];
    const int deg = g_cnt[w];
    const float erd = g_er[w];

    float ssum = 0.f;
    for (int t = lane; t < deg; t += 32) {
        int s = g_srcs[beg + t];
        ssum += __expf(lrelu_clamp(g_el[s] + erd));
    }
#pragma unroll
    for (int o = 16; o > 0; o >>= 1) ssum += __shfl_xor_sync(0xffffffffu, ssum, o);
    const float inv = __frcp_rn(ssum);

    float a0 = 0.f, a1 = 0.f;
    for (int c0 = 0; c0 < deg; c0 += 32) {
        int t = c0 + lane;
        float av = 0.f;
        int sidx = 0;
        if (t < deg) {
            sidx = g_srcs[beg + t];
            av = __expf(lrelu_clamp(g_el[sidx] + erd)) * inv;
        }
        sal[wl][lane] = av;
        ssrc[wl][lane] = sidx;
        __syncwarp();
        int lim = min(32, deg - c0);
        for (int j = 0; j < lim; j++) {
            float aj = sal[wl][j];
            const float* zr = g_z1 + (size_t)ssrc[wl][j] * 40;
            a0 = fmaf(aj, zr[lane], a0);
            if (lane < 8) a1 = fmaf(aj, zr[32 + lane], a1);
        }
        __syncwarp();
    }
    float v = a0 + b1[lane];
    out[(size_t)w * 40 + lane] = v > 0.f ? v : (__expf(v) - 1.f);
    if (lane < 8) {
        v = a1 + b1[32 + lane];
        out[(size_t)w * 40 + 32 + lane] = v > 0.f ? v : (__expf(v) - 1.f);
    }
    __syncwarp();
    if (lane == 0) g_cnt[w] = 0;   // restore all-zero invariant for next call
}

// ---------------- launch: fork-join two-stream overlap (CSR chain || GEMM chain) ----------------
extern "C" void kernel_launch(void* const* d_in, const int* in_sizes, int n_in,
                              void* d_out, int out_size) {
    const float* x   = (const float*)d_in[0];
    const int*   src = (const int*)d_in[1];
    const int*   dst = (const int*)d_in[2];
    const float* W0  = (const float*)d_in[3];
    const float* al0 = (const float*)d_in[4];
    const float* ar0 = (const float*)d_in[5];
    const float* b0  = (const float*)d_in[6];
    const float* W1  = (const float*)d_in[7];
    const float* al1 = (const float*)d_in[8];
    const float* ar1 = (const float*)d_in[9];
    const float* b1  = (const float*)d_in[10];
    float* out = (float*)d_out;

    const int E  = in_sizes[1];
    const int EP = E + NN;

    // one-time stream/event setup (host-side objects only; no device memory)
    static cudaStream_t s1 = nullptr, s2 = nullptr;
    static cudaEvent_t evA = nullptr, evB = nullptr, evC = nullptr;
    if (s1 == nullptr) {
        cudaStreamCreateWithFlags(&s1, cudaStreamNonBlocking);
        cudaStreamCreateWithFlags(&s2, cudaStreamNonBlocking);
        cudaEventCreateWithFlags(&evA, cudaEventDisableTiming);
        cudaEventCreateWithFlags(&evB, cudaEventDisableTiming);
        cudaEventCreateWithFlags(&evC, cudaEventDisableTiming);
    }

    // fork from the (captured) legacy stream
    cudaEventRecord(evA, 0);
    cudaStreamWaitEvent(s1, evA, 0);
    cudaStreamWaitEvent(s2, evA, 0);

    // CSR chain on s1
    csr_count_kernel<<<(EP + 255) / 256, 256, 0, s1>>>(src, dst, E);           // 0
    scanall_kernel<<<NB_SCAN, 512, 0, s1>>>();                                 // 1
    // GEMM chain on s2
    wconv_kernel<<<(128 * 256 + 128 * 40 + 255) / 256, 256, 0, s2>>>(W0, W1);  // 2
    gemm0_mma_kernel<<<(NN + 127) / 128, 256, 0, s2>>>(x, al0, ar0, NN);       // 3 <- profiled
    csr_scatter_kernel<<<(EP + 255) / 256, 256, 0, s1>>>(src, dst, E);         // 4

    // join: gather0 needs CSR (s1) + gemm0 (s2)
    cudaEventRecord(evB, s1);
    cudaStreamWaitEvent(s2, evB, 0);

    gather0_kernel<<<(NN * 32 + 255) / 256, 256, 0, s2>>>(b0);                 // 5
    gemm1_mma_kernel<<<(NN + 127) / 128, 128, 0, s2>>>(al1, ar1, NN);          // 6
    gather1_kernel<<<(NN * 32 + 255) / 256, 256, 0, s2>>>(out, b1);            // 7

    // join back to the captured stream
    cudaEventRecord(evC, s2);
    cudaStreamWaitEvent(0, evC, 0);
}